// round 3
// baseline (speedup 1.0000x reference)
#include <cuda_runtime.h>
#include <math.h>

#define H 1024
#define W 1024
#define BATCH 16
#define CH 3
#define NPLANE (H * W)
#define NPIX (BATCH * NPLANE)

#define G0 0.13533528323661270f  /* exp(-2)   */
#define G1 0.60653065971263342f  /* exp(-0.5) */

/* ================================================================== */
/* Kernel 1: separable 5x5 Gaussian blur, register-rolling vertical   */
/* 128 threads, tile 128x32, one column per thread                    */
/* ================================================================== */
#define BX 128
#define BY 32

__global__ __launch_bounds__(128) void blur_kernel(
    const float* __restrict__ img,
    const float* __restrict__ bh_p,
    const float* __restrict__ bv_p,
    float* __restrict__ out)
{
    __shared__ float s_in[BY + 4][BX + 5];   /* 36 x 133 */

    const float bh = __ldg(bh_p);
    const float bv = __ldg(bv_p);

    const int plane = blockIdx.z;
    const int x0 = blockIdx.x * BX;
    const int y0 = blockIdx.y * BY;
    const float* src = img + (size_t)plane * NPLANE;
    float* dst = out + (size_t)plane * NPLANE;
    const int tid = threadIdx.x;

    const bool interior = (x0 >= 2) && (x0 + BX + 2 <= W) &&
                          (y0 >= 2) && (y0 + BY + 2 <= H);

    if (interior) {
        const float* p = src + (size_t)(y0 - 2) * W + (x0 - 2);
        #pragma unroll
        for (int rr = 0; rr < BY + 4; rr++) {
            s_in[rr][tid] = p[tid];
            if (tid < 4) s_in[rr][tid + BX] = p[tid + BX];
            p += W;
        }
    } else {
        for (int rr = 0; rr < BY + 4; rr++) {
            const int gy = y0 + rr - 2;
            const bool rowok = (gy >= 0 && gy < H);
            for (int c = tid; c < BX + 4; c += BX) {
                const int gx = x0 + c - 2;
                float v = 0.0f;
                if (rowok && gx >= 0 && gx < W) v = src[(size_t)gy * W + gx];
                s_in[rr][c] = v;
            }
        }
    }
    __syncthreads();

    const int x = tid;

    /* horizontal blur for smem row rr; 0 for out-of-image rows */
    #define HROW(rr) \
        (((y0 + (rr) - 2) >= 0 && (y0 + (rr) - 2) < H) \
            ? (G0 * (s_in[rr][x] + s_in[rr][x + 4]) \
             + G1 * (s_in[rr][x + 1] + s_in[rr][x + 3]) \
             + s_in[rr][x + 2] + bh) \
            : 0.0f)

    float h0 = HROW(0), h1 = HROW(1), h2 = HROW(2), h3 = HROW(3);
    float* drow = dst + (size_t)y0 * W + x0 + x;

    #pragma unroll 8
    for (int r = 0; r < BY; r++) {
        const float h4 = HROW(r + 4);
        *drow = G0 * (h0 + h4) + G1 * (h1 + h3) + h2 + bv;
        h0 = h1; h1 = h2; h2 = h3; h3 = h4;
        drow += W;
    }
    #undef HROW
}

/* ================================================================== */
/* Kernel 2: fused Sobel + orientation + NMS + thresholds             */
/* block 32x16, mag/sgx/sgy accumulated in smem over 1-halo region    */
/* ================================================================== */
#define FX 32
#define FY 16
#define MW 34                 /* mag region width  = FX+2 */
#define MH 18                 /* mag region height = FY+2 */
#define MS 36                 /* mag row stride (padded)  */

__global__ __launch_bounds__(512) void sobel_nms_kernel(
    const float* __restrict__ blurred,
    const float* __restrict__ shb_p,
    const float* __restrict__ svb_p,
    const float* __restrict__ d0b_p,
    const float* __restrict__ d1b_p,
    float* __restrict__ gm_out,
    float* __restrict__ orient_out,
    float* __restrict__ early_out,
    float* __restrict__ thin_out,
    float* __restrict__ thresh_out)
{
    __shared__ float s_b[FY + 4][FX + 5];      /* 20 x 37 blurred tile, halo 2 */
    __shared__ float s_mag[MH][MS];
    __shared__ float s_gx[MH][MS];
    __shared__ float s_gy[MH][MS];

    const float shb = __ldg(shb_p);
    const float svb = __ldg(svb_p);
    const float d0b = __ldg(d0b_p);
    const float d1b = __ldg(d1b_p);

    const int b = blockIdx.z;
    const int x0 = blockIdx.x * FX;
    const int y0 = blockIdx.y * FY;
    const int tx = threadIdx.x, ty = threadIdx.y;
    const int tlin = ty * FX + tx;

    /* zero accumulation arrays */
    for (int i = tlin; i < MH * MS; i += FX * FY) {
        ((float*)s_mag)[i] = 0.0f;
        ((float*)s_gx)[i] = 0.0f;
        ((float*)s_gy)[i] = 0.0f;
    }

    #pragma unroll
    for (int c = 0; c < CH; ++c) {
        __syncthreads();
        const float* src = blurred + ((size_t)(b * CH + c)) * NPLANE;
        /* load blurred tile with 2-halo, zero OOB: 20x36 = 720 elems */
        for (int i = tlin; i < (FY + 4) * (FX + 4); i += FX * FY) {
            const int r = i / (FX + 4), cc = i % (FX + 4);
            const int gy = y0 + r - 2, gx = x0 + cc - 2;
            float v = 0.0f;
            if (gy >= 0 && gy < H && gx >= 0 && gx < W) v = src[(size_t)gy * W + gx];
            s_b[r][cc] = v;
        }
        __syncthreads();

        /* sobel + magnitude over mag region (tile + 1-halo): 34x18 = 612 */
        for (int i = tlin; i < MW * MH; i += FX * FY) {
            const int my = i / MW, mx = i % MW;
            const int gy = y0 + my - 1, gx = x0 + mx - 1;
            if (gy >= 0 && gy < H && gx >= 0 && gx < W) {
                /* position maps to s_b[my+1][mx+1] */
                const float a00 = s_b[my][mx],     a01 = s_b[my][mx + 1],     a02 = s_b[my][mx + 2];
                const float a10 = s_b[my + 1][mx],                            a12 = s_b[my + 1][mx + 2];
                const float a20 = s_b[my + 2][mx], a21 = s_b[my + 2][mx + 1], a22 = s_b[my + 2][mx + 2];

                const float gxv = (a00 - a02) + 2.0f * (a10 - a12) + (a20 - a22) + shb;
                const float gyv = (a00 + 2.0f * a01 + a02) - (a20 + 2.0f * a21 + a22) + svb;

                s_mag[my][mx] += sqrtf(gxv * gxv + gyv * gyv);
                s_gx[my][mx] += gxv;
                s_gy[my][mx] += gyv;
            }
        }
    }
    __syncthreads();

    /* per-pixel outputs */
    const int mx = tx + 1, my = ty + 1;
    const float mag = s_mag[my][mx];
    const float sgx = s_gx[my][mx];
    const float sgy = s_gy[my][mx];

    const size_t p = (size_t)b * NPLANE + (size_t)(y0 + ty) * W + x0 + tx;

    gm_out[p] = mag;

    float go = atan2f(sgy, sgx) * (180.0f / 3.14159f);
    if (go < 0.0f) go = 360.0f + go;
    go = fmodf(go, 180.0f);
    const float orient = rintf(go / 45.0f) * 45.0f;
    orient_out[p] = orient;

    early_out[p] = (mag < 10.0f) ? 0.0f : mag;

    /* NMS: orientation picks one directional filter */
    const int k = (int)(orient * (1.0f / 45.0f) + 0.5f);   /* 0..4 */
    const int di = (k >= 1 && k <= 3) ? 1 : 0;
    const int dj = (k < 2) ? 1 : ((k == 2) ? 0 : -1);
    const float bias = (k < 4) ? d0b : d1b;

    const int gyn = y0 + ty + di;
    const int gxn = x0 + tx + dj;
    float nbv = 0.0f;
    if (gyn < H && gxn >= 0 && gxn < W)
        nbv = s_mag[my + di][mx + dj];

    const float val = mag - nbv + bias;
    const float t = (val > 0.0f) ? mag : 0.0f;
    thin_out[p] = t;
    thresh_out[p] = (t < 10.0f) ? 0.0f : t;
}

/* ================================================================== */
extern "C" void kernel_launch(void* const* d_in, const int* in_sizes, int n_in,
                              void* d_out, int out_size)
{
    const float* img = (const float*)d_in[0];
    const float* bh  = (const float*)d_in[1];
    const float* bv  = (const float*)d_in[2];
    const float* shb = (const float*)d_in[3];
    const float* svb = (const float*)d_in[4];
    const float* d0b = (const float*)d_in[5];
    const float* d1b = (const float*)d_in[6];

    float* out     = (float*)d_out;
    float* blurred = out;                          /* 3*NPIX */
    float* gm      = out + (size_t)3 * NPIX;
    float* orient  = gm + NPIX;
    float* thin    = orient + NPIX;
    float* thresh  = thin + NPIX;
    float* early   = thresh + NPIX;

    dim3 g1(W / BX, H / BY, BATCH * CH);
    blur_kernel<<<g1, BX>>>(img, bh, bv, blurred);

    dim3 b2(FX, FY);
    dim3 g2(W / FX, H / FY, BATCH);
    sobel_nms_kernel<<<g2, b2>>>(blurred, shb, svb, d0b, d1b,
                                 gm, orient, early, thin, thresh);

    (void)in_sizes; (void)n_in; (void)out_size;
}

// round 4
// speedup vs baseline: 1.4406x; 1.4406x over previous
#include <cuda_runtime.h>
#include <math.h>

#define H 1024
#define W 1024
#define BATCH 16
#define CH 3
#define NPLANE (H * W)
#define NPIX (BATCH * NPLANE)

#define G0 0.13533528323661270f  /* exp(-2)   */
#define G1 0.60653065971263342f  /* exp(-0.5) */

/* ================================================================== */
/* Kernel 1: separable 5x5 Gaussian blur, register-rolling vertical   */
/* 128 threads, tile 128x32, one column per thread (R3 version)       */
/* ================================================================== */
#define BX 128
#define BY 32

__global__ __launch_bounds__(128) void blur_kernel(
    const float* __restrict__ img,
    const float* __restrict__ bh_p,
    const float* __restrict__ bv_p,
    float* __restrict__ out)
{
    __shared__ float s_in[BY + 4][BX + 5];   /* 36 x 133 */

    const float bh = __ldg(bh_p);
    const float bv = __ldg(bv_p);

    const int plane = blockIdx.z;
    const int x0 = blockIdx.x * BX;
    const int y0 = blockIdx.y * BY;
    const float* src = img + (size_t)plane * NPLANE;
    float* dst = out + (size_t)plane * NPLANE;
    const int tid = threadIdx.x;

    const bool interior = (x0 >= 2) && (x0 + BX + 2 <= W) &&
                          (y0 >= 2) && (y0 + BY + 2 <= H);

    if (interior) {
        const float* p = src + (size_t)(y0 - 2) * W + (x0 - 2);
        #pragma unroll
        for (int rr = 0; rr < BY + 4; rr++) {
            s_in[rr][tid] = p[tid];
            if (tid < 4) s_in[rr][tid + BX] = p[tid + BX];
            p += W;
        }
    } else {
        for (int rr = 0; rr < BY + 4; rr++) {
            const int gy = y0 + rr - 2;
            const bool rowok = (gy >= 0 && gy < H);
            for (int c = tid; c < BX + 4; c += BX) {
                const int gx = x0 + c - 2;
                float v = 0.0f;
                if (rowok && gx >= 0 && gx < W) v = src[(size_t)gy * W + gx];
                s_in[rr][c] = v;
            }
        }
    }
    __syncthreads();

    const int x = tid;

    #define HROW(rr) \
        (((y0 + (rr) - 2) >= 0 && (y0 + (rr) - 2) < H) \
            ? (G0 * (s_in[rr][x] + s_in[rr][x + 4]) \
             + G1 * (s_in[rr][x + 1] + s_in[rr][x + 3]) \
             + s_in[rr][x + 2] + bh) \
            : 0.0f)

    float h0 = HROW(0), h1 = HROW(1), h2 = HROW(2), h3 = HROW(3);
    float* drow = dst + (size_t)y0 * W + x0 + x;

    #pragma unroll 8
    for (int r = 0; r < BY; r++) {
        const float h4 = HROW(r + 4);
        *drow = G0 * (h0 + h4) + G1 * (h1 + h3) + h2 + bv;
        h0 = h1; h1 = h2; h2 = h3; h3 = h4;
        drow += W;
    }
    #undef HROW
}

/* ================================================================== */
/* Kernel 2: fused Sobel + orientation + NMS, column-rolling          */
/* 128 threads, tile 128x32, one column per thread                    */
/* Rolling 3-row rings: blurred (3ch) and mag                         */
/* ================================================================== */
#define FTX 128
#define FTY 32
#define SBS 132   /* s_b row width: cols x0-2 .. x0+129 */
#define SMS 132   /* s_mag row width: cols x0-1 .. x0+128 at idx 0..129 */

__global__ __launch_bounds__(128) void sobel_nms_kernel(
    const float* __restrict__ blurred,
    const float* __restrict__ shb_p,
    const float* __restrict__ svb_p,
    const float* __restrict__ d0b_p,
    const float* __restrict__ d1b_p,
    float* __restrict__ gm_out,
    float* __restrict__ orient_out,
    float* __restrict__ early_out,
    float* __restrict__ thin_out,
    float* __restrict__ thresh_out)
{
    __shared__ float s_b[CH][3][SBS];
    __shared__ float s_mag[3][SMS];

    const float shb = __ldg(shb_p);
    const float svb = __ldg(svb_p);
    const float d0b = __ldg(d0b_p);
    const float d1b = __ldg(d1b_p);

    const int b  = blockIdx.z;
    const int x0 = blockIdx.x * FTX;
    const int y0 = blockIdx.y * FTY;
    const int t  = threadIdx.x;

    const float* bl = blurred + (size_t)b * CH * NPLANE;

    /* load blurred row gy (all 3 channels) into ring slot; OOB -> 0 */
    auto load_row = [&](int gy, int slot) {
        const bool rowok = (gy >= 0 && gy < H);
        const int gx = x0 - 2 + t;
        const bool c0ok = rowok && gx >= 0 && gx < W;
        const int gx2 = x0 + 126 + t;
        const bool c1ok = rowok && (t < 4) && gx2 < W;
        const size_t rbase = rowok ? (size_t)gy * W : 0;
        #pragma unroll
        for (int c = 0; c < CH; c++) {
            const float* src = bl + (size_t)c * NPLANE + rbase;
            s_b[c][slot][t] = c0ok ? src[gx] : 0.0f;
            if (t < 4) s_b[c][slot][128 + t] = c1ok ? src[gx2] : 0.0f;
        }
    };

    /* 3-channel sobel at blurred col index bc (center), slots sp/sc/sn */
    auto sobel3 = [&](int sp, int sc, int sn, int bc,
                      float& mag, float& gxs, float& gys) {
        mag = 0.0f; gxs = 0.0f; gys = 0.0f;
        #pragma unroll
        for (int c = 0; c < CH; c++) {
            const float a00 = s_b[c][sp][bc - 1], a01 = s_b[c][sp][bc], a02 = s_b[c][sp][bc + 1];
            const float a10 = s_b[c][sc][bc - 1],                       a12 = s_b[c][sc][bc + 1];
            const float a20 = s_b[c][sn][bc - 1], a21 = s_b[c][sn][bc], a22 = s_b[c][sn][bc + 1];
            const float gxv = (a00 - a02) + 2.0f * (a10 - a12) + (a20 - a22) + shb;
            const float gyv = (a00 + 2.0f * a01 + a02) - (a20 + 2.0f * a21 + a22) + svb;
            mag += sqrtf(gxv * gxv + gyv * gyv);
            gxs += gxv; gys += gyv;
        }
    };

    load_row(y0 - 2, 0);
    load_row(y0 - 1, 1);
    load_row(y0,     2);
    __syncthreads();

    float pm = 0.0f, pgx = 0.0f, pgy = 0.0f;   /* center values of prev mag row */

    for (int r = 0; r < FTY + 2; r++) {
        const int my = y0 - 1 + r;               /* mag row being computed */
        const int sp = r % 3, sc = (r + 1) % 3, sn = (r + 2) % 3;
        const int mslot = r % 3;

        float nm = 0.0f, ngx = 0.0f, ngy = 0.0f;
        if (my < H && my >= 0) {                 /* my>=0 only fails for y0==0,r==0 */
            sobel3(sp, sc, sn, t + 2, nm, ngx, ngy);
            s_mag[mslot][t + 1] = nm;
            if (t == 0) {
                float hm = 0.0f, hx, hy;
                if (x0 > 0) sobel3(sp, sc, sn, 1, hm, hx, hy);
                s_mag[mslot][0] = hm;
            }
            if (t == 127) {
                float hm = 0.0f, hx, hy;
                if (x0 + FTX < W) sobel3(sp, sc, sn, 130, hm, hx, hy);
                s_mag[mslot][129] = hm;
            }
        } else {
            s_mag[mslot][t + 1] = 0.0f;
            if (t == 0)   s_mag[mslot][0]   = 0.0f;
            if (t == 127) s_mag[mslot][129] = 0.0f;
        }
        __syncthreads();

        if (r >= 2) {
            const int yo = y0 + r - 2;
            const size_t p = (size_t)b * NPLANE + (size_t)yo * W + x0 + t;
            const float mag = pm;

            gm_out[p] = mag;

            float go = atan2f(pgy, pgx) * (180.0f / 3.14159f);
            if (go < 0.0f) go = 360.0f + go;
            go = fmodf(go, 180.0f);
            const float orient = rintf(go / 45.0f) * 45.0f;
            orient_out[p] = orient;

            early_out[p] = (mag < 10.0f) ? 0.0f : mag;

            const int k = (int)(orient * (1.0f / 45.0f) + 0.5f);  /* 0..4 */
            const int di = (k >= 1 && k <= 3) ? 1 : 0;
            const int dj = (k < 2) ? 1 : ((k == 2) ? 0 : -1);
            const float bias = (k < 4) ? d0b : d1b;

            /* neighbor row: yo (slot (r-1)%3) or yo+1 (slot r%3) */
            const int nslot = di ? (r % 3) : ((r + 2) % 3);  /* (r-1)%3 == (r+2)%3 */
            const float nbv = s_mag[nslot][t + 1 + dj];      /* halo/OOB already 0 */

            const float val = mag - nbv + bias;
            const float th = (val > 0.0f) ? mag : 0.0f;
            thin_out[p] = th;
            thresh_out[p] = (th < 10.0f) ? 0.0f : th;
        }

        if (r < FTY + 1) load_row(y0 + 1 + r, r % 3);

        pm = nm; pgx = ngx; pgy = ngy;
        __syncthreads();
    }
}

/* ================================================================== */
extern "C" void kernel_launch(void* const* d_in, const int* in_sizes, int n_in,
                              void* d_out, int out_size)
{
    const float* img = (const float*)d_in[0];
    const float* bh  = (const float*)d_in[1];
    const float* bv  = (const float*)d_in[2];
    const float* shb = (const float*)d_in[3];
    const float* svb = (const float*)d_in[4];
    const float* d0b = (const float*)d_in[5];
    const float* d1b = (const float*)d_in[6];

    float* out     = (float*)d_out;
    float* blurred = out;                          /* 3*NPIX */
    float* gm      = out + (size_t)3 * NPIX;
    float* orient  = gm + NPIX;
    float* thin    = orient + NPIX;
    float* thresh  = thin + NPIX;
    float* early   = thresh + NPIX;

    dim3 g1(W / BX, H / BY, BATCH * CH);
    blur_kernel<<<g1, BX>>>(img, bh, bv, blurred);

    dim3 g2(W / FTX, H / FTY, BATCH);
    sobel_nms_kernel<<<g2, 128>>>(blurred, shb, svb, d0b, d1b,
                                  gm, orient, early, thin, thresh);

    (void)in_sizes; (void)n_in; (void)out_size;
}

// round 5
// speedup vs baseline: 1.5480x; 1.0745x over previous
#include <cuda_runtime.h>
#include <math.h>

#define H 1024
#define W 1024
#define BATCH 16
#define CH 3
#define NPLANE (H * W)
#define NPIX (BATCH * NPLANE)

#define G0 0.13533528323661270f  /* exp(-2)   */
#define G1 0.60653065971263342f  /* exp(-0.5) */

#define TX 128      /* tile width (outputs)  */
#define TY 32       /* tile height (outputs) */
#define NT 160      /* threads per block     */
#define LW 136      /* img row width loaded  : cols x0-4 .. x0+131 */
#define BW 132      /* blurred row width     : cols x0-2 .. x0+129 */
#define MWID 130    /* mag row width         : cols x0-1 .. x0+128 */

__global__ __launch_bounds__(NT) void canny_kernel(
    const float* __restrict__ img,
    const float* __restrict__ bh_p,  const float* __restrict__ bv_p,
    const float* __restrict__ shb_p, const float* __restrict__ svb_p,
    const float* __restrict__ d0b_p, const float* __restrict__ d1b_p,
    float* __restrict__ blurred_out,
    float* __restrict__ gm_out,   float* __restrict__ orient_out,
    float* __restrict__ thin_out, float* __restrict__ thresh_out,
    float* __restrict__ early_out)
{
    __shared__ float s_img[CH][LW];
    __shared__ float s_bl[CH][LW];
    __shared__ float s_mag[2][LW];
    __shared__ float s_gx[2][LW];
    __shared__ float s_gy[2][LW];

    const float bh  = __ldg(bh_p),  bv  = __ldg(bv_p);
    const float shb = __ldg(shb_p), svb = __ldg(svb_p);
    const float d0b = __ldg(d0b_p), d1b = __ldg(d1b_p);

    const int b  = blockIdx.z;
    const int x0 = blockIdx.x * TX;
    const int y0 = blockIdx.y * TY;
    const int t  = threadIdx.x;

    const float* imgb = img + (size_t)b * CH * NPLANE;
    float* blb = blurred_out + (size_t)b * CH * NPLANE;

    /* register rings */
    float h[CH][5];                /* h-blurred rows (vertical blur ring)   */
    float hs[CH][3], hd[CH][3];    /* sobel horizontal sums/diffs ring      */
    #pragma unroll
    for (int c = 0; c < CH; c++) {
        #pragma unroll
        for (int k = 0; k < 5; k++) h[c][k] = 0.0f;
        #pragma unroll
        for (int k = 0; k < 3; k++) { hs[c][k] = 0.0f; hd[c][k] = 0.0f; }
    }

    const int gxl = x0 - 4 + t;                               /* img load col */
    const bool cAok = (gxl >= 0) && (gxl < W);
    const int colB = x0 - 2 + t;                              /* blurred col  */
    const bool cBok = (colB >= 0) && (colB < W);
    const int colM = x0 - 1 + t;                              /* mag col      */
    const bool cMok = (colM >= 0) && (colM < W);

    #pragma unroll 2
    for (int i = 0; i < TY + 8; i++) {
        const int y_img = y0 - 4 + i;   /* img row loaded this iteration */
        const int yb = y_img - 2;       /* blurred row produced          */
        const int ym = yb - 1;          /* mag row produced              */
        const int yo = ym - 1;          /* output row written            */
        const bool rAok = (y_img >= 0) && (y_img < H);

        /* ---- A: load img row (3 channels), zero OOB ---- */
        if (t < LW) {
            const size_t roff = rAok ? ((size_t)y_img * W + gxl) : 0;
            const bool ok = rAok && cAok;
            #pragma unroll
            for (int c = 0; c < CH; c++)
                s_img[c][t] = ok ? imgb[(size_t)c * NPLANE + roff] : 0.0f;
        }
        __syncthreads();

        /* ---- B: horizontal blur + vertical ring -> blurred row ---- */
        if (t < BW) {
            const bool rBok = (yb >= 0) && (yb < H);
            const bool wr = rBok && (yb >= y0) && (yb < y0 + TY) && (t >= 2) && (t < 2 + TX);
            #pragma unroll
            for (int c = 0; c < CH; c++) {
                const float v0 = s_img[c][t],     v1 = s_img[c][t + 1],
                            v2 = s_img[c][t + 2], v3 = s_img[c][t + 3],
                            v4 = s_img[c][t + 4];
                const float hn = rAok ? (G0 * (v0 + v4) + G1 * (v1 + v3) + v2 + bh) : 0.0f;
                h[c][0] = h[c][1]; h[c][1] = h[c][2]; h[c][2] = h[c][3]; h[c][3] = h[c][4];
                h[c][4] = hn;
                const float B = G0 * (h[c][0] + h[c][4]) + G1 * (h[c][1] + h[c][3]) + h[c][2] + bv;
                s_bl[c][t] = (rBok && cBok) ? B : 0.0f;   /* sobel's zero-padded view */
                if (wr) blb[(size_t)c * NPLANE + (size_t)yb * W + (x0 + t - 2)] = B;
            }
        }
        __syncthreads();

        /* ---- C: separable sobel rings -> mag/gx/gy row ---- */
        if (t < MWID) {
            float mag = 0.0f, sgx = 0.0f, sgy = 0.0f;
            #pragma unroll
            for (int c = 0; c < CH; c++) {
                const float b0 = s_bl[c][t], b1 = s_bl[c][t + 1], b2 = s_bl[c][t + 2];
                const float hsn = b0 + 2.0f * b1 + b2;
                const float hdn = b0 - b2;
                hs[c][0] = hs[c][1]; hs[c][1] = hs[c][2]; hs[c][2] = hsn;
                hd[c][0] = hd[c][1]; hd[c][1] = hd[c][2]; hd[c][2] = hdn;
                const float gxv = (hd[c][0] + 2.0f * hd[c][1]) + hd[c][2] + shb;
                const float gyv = hs[c][0] - hs[c][2] + svb;
                mag += sqrtf(gxv * gxv + gyv * gyv);
                sgx += gxv;
                sgy += gyv;
            }
            const bool rMok = (ym >= 0) && (ym < H);
            const int sl = i & 1;
            s_mag[sl][t] = (rMok && cMok) ? mag : 0.0f;
            s_gx[sl][t] = sgx;
            s_gy[sl][t] = sgy;
        }
        __syncthreads();

        /* ---- D: orientation + NMS + all 5 per-pixel outputs ---- */
        if ((t < TX) && (i >= 8)) {
            const int slC = (i - 1) & 1;   /* mag row yo   */
            const int slN = i & 1;         /* mag row yo+1 */
            const float mag = s_mag[slC][t + 1];
            const float sgx = s_gx[slC][t + 1];
            const float sgy = s_gy[slC][t + 1];
            const size_t p = (size_t)b * NPLANE + (size_t)yo * W + x0 + t;

            gm_out[p] = mag;

            float go = atan2f(sgy, sgx) * (180.0f / 3.14159f);
            if (go < 0.0f) go = 360.0f + go;
            go = fmodf(go, 180.0f);
            const float orient = rintf(go / 45.0f) * 45.0f;
            orient_out[p] = orient;

            early_out[p] = (mag < 10.0f) ? 0.0f : mag;

            const int k = (int)(orient * (1.0f / 45.0f) + 0.5f);   /* 0..4 */
            const int di = (k >= 1 && k <= 3) ? 1 : 0;
            const int dj = (k < 2) ? 1 : ((k == 2) ? 0 : -1);
            const float bias = (k < 4) ? d0b : d1b;

            const float nbv = s_mag[di ? slN : slC][t + 1 + dj];   /* OOB already 0 */
            const float val = mag - nbv + bias;
            const float th = (val > 0.0f) ? mag : 0.0f;
            thin_out[p] = th;
            thresh_out[p] = (th < 10.0f) ? 0.0f : th;
        }
        /* no sync needed here: next writes to s_img/s_bl/s_mag are all
           separated from this iteration's reads by the S1/S2 barriers */
    }
}

/* ================================================================== */
extern "C" void kernel_launch(void* const* d_in, const int* in_sizes, int n_in,
                              void* d_out, int out_size)
{
    const float* img = (const float*)d_in[0];
    const float* bh  = (const float*)d_in[1];
    const float* bv  = (const float*)d_in[2];
    const float* shb = (const float*)d_in[3];
    const float* svb = (const float*)d_in[4];
    const float* d0b = (const float*)d_in[5];
    const float* d1b = (const float*)d_in[6];

    float* out     = (float*)d_out;
    float* blurred = out;                          /* 3*NPIX */
    float* gm      = out + (size_t)3 * NPIX;
    float* orient  = gm + NPIX;
    float* thin    = orient + NPIX;
    float* thresh  = thin + NPIX;
    float* early   = thresh + NPIX;

    dim3 grid(W / TX, H / TY, BATCH);
    canny_kernel<<<grid, NT>>>(img, bh, bv, shb, svb, d0b, d1b,
                               blurred, gm, orient, thin, thresh, early);

    (void)in_sizes; (void)n_in; (void)out_size;
}

// round 7
// speedup vs baseline: 1.8336x; 1.1845x over previous
#include <cuda_runtime.h>
#include <math.h>

#define H 1024
#define W 1024
#define BATCH 16
#define CH 3
#define NPLANE (H * W)
#define NPIX (BATCH * NPLANE)

#define G0 0.13533528323661270f  /* exp(-2)   */
#define G1 0.60653065971263342f  /* exp(-0.5) */

#define TX 128      /* tile width (outputs)  */
#define TY 64       /* tile height (outputs) */
#define NT 160      /* threads per block     */
#define LW 136      /* img row width loaded  : cols x0-4 .. x0+131 */
#define BW 132      /* blurred row width     : cols x0-2 .. x0+129 */
#define MW2 130     /* mag cols              : x0-1 .. x0+128       */

template<bool INTERIOR>
__device__ __forceinline__ void canny_body(
    const float* __restrict__ imgb,   /* img  + b*3*NPLANE */
    float* __restrict__ blb,          /* blur + b*3*NPLANE */
    float* __restrict__ out,
    int b, int x0, int y0, int t,
    float bh, float bv, float shb, float svb, float d0b, float d1b,
    float (*s_img)[LW], float (*s_bl)[LW], float (*s_mag)[LW])
{
    /* register rings */
    float h0[CH], h1[CH], h2[CH], h3[CH], h4[CH];            /* vertical blur */
    float hs0[CH], hs1[CH], hs2[CH];                         /* sobel h-sums  */
    float hd0[CH], hd1[CH], hd2[CH];                         /* sobel h-diffs */
    #pragma unroll
    for (int c = 0; c < CH; c++) {
        h0[c] = h1[c] = h2[c] = h3[c] = h4[c] = 0.0f;
        hs0[c] = hs1[c] = hs2[c] = 0.0f;
        hd0[c] = hd1[c] = hd2[c] = 0.0f;
    }
    float pm = 0.0f, pgx = 0.0f, pgy = 0.0f;   /* prev mag row, own column */

    const int gxl = x0 - 4 + t;                           /* img load col   */
    const bool cAok = INTERIOR || ((gxl >= 0) && (gxl < W));
    const int colB = x0 - 2 + t;                          /* blurred col    */
    const bool cBok = INTERIOR || ((colB >= 0) && (colB < W));

    /* phase-C column assignment: t<128 -> col x0+t (own output column),
       t==128 -> halo col x0-1, t==129 -> halo col x0+128 */
    int ib, im; bool cMok;
    if (t < TX)       { ib = t + 2;  im = t + 1;  cMok = true; }
    else if (t == TX) { ib = 1;      im = 0;      cMok = INTERIOR || (x0 > 0); }
    else              { ib = TX + 2; im = TX + 1; cMok = INTERIOR || (x0 + TX < W); }

    const size_t pbase = (size_t)b * NPLANE + (size_t)y0 * W + x0 + t;

    float* gm_out     = out + (size_t)3 * NPIX;
    float* orient_out = out + (size_t)4 * NPIX;
    float* thin_out   = out + (size_t)5 * NPIX;
    float* thresh_out = out + (size_t)6 * NPIX;
    float* early_out  = out + (size_t)7 * NPIX;

    #pragma unroll 2
    for (int i = 0; i < TY + 8; i++) {
        const int y_img = y0 - 4 + i;       /* img row loaded    */
        const int yb = y_img - 2;           /* blurred row made  */
        const int ym = yb - 1;              /* mag row made      */
        const bool rAok = INTERIOR || ((y_img >= 0) && (y_img < H));

        /* ---- A: load img row (3 channels) ---- */
        if (t < LW) {
            if (INTERIOR) {
                const size_t ro = (size_t)y_img * W + gxl;
                #pragma unroll
                for (int c = 0; c < CH; c++)
                    s_img[c][t] = imgb[(size_t)c * NPLANE + ro];
            } else {
                const bool ok = rAok && cAok;
                const size_t ro = ok ? ((size_t)y_img * W + gxl) : 0;
                #pragma unroll
                for (int c = 0; c < CH; c++)
                    s_img[c][t] = ok ? imgb[(size_t)c * NPLANE + ro] : 0.0f;
            }
        }
        __syncthreads();

        /* ---- B: horizontal blur + vertical ring -> blurred row ---- */
        if (t < BW) {
            const bool rBok = INTERIOR || ((yb >= 0) && (yb < H));
            const bool wr = (yb >= y0) && (yb < y0 + TY) && (t >= 2) && (t < 2 + TX);
            float* wp = blb + ((size_t)yb * W + (x0 + t - 2));
            #pragma unroll
            for (int c = 0; c < CH; c++) {
                const float v0 = s_img[c][t],     v1 = s_img[c][t + 1],
                            v2 = s_img[c][t + 2], v3 = s_img[c][t + 3],
                            v4 = s_img[c][t + 4];
                float hn = G0 * (v0 + v4) + G1 * (v1 + v3) + v2 + bh;
                if (!INTERIOR && !rAok) hn = 0.0f;
                h0[c] = h1[c]; h1[c] = h2[c]; h2[c] = h3[c]; h3[c] = h4[c]; h4[c] = hn;
                const float B = G0 * (h0[c] + h4[c]) + G1 * (h1[c] + h3[c]) + h2[c] + bv;
                s_bl[c][t] = (INTERIOR || (rBok && cBok)) ? B : 0.0f;
                if (wr) wp[(size_t)c * NPLANE] = B;
            }
        }
        __syncthreads();

        /* ---- C: separable sobel rings -> mag row ---- */
        float nm = 0.0f, ngx = 0.0f, ngy = 0.0f;
        if (t < MW2) {
            #pragma unroll
            for (int c = 0; c < CH; c++) {
                const float b0 = s_bl[c][ib - 1], b1 = s_bl[c][ib], b2 = s_bl[c][ib + 1];
                const float hsn = b0 + 2.0f * b1 + b2;
                const float hdn = b0 - b2;
                hs0[c] = hs1[c]; hs1[c] = hs2[c]; hs2[c] = hsn;
                hd0[c] = hd1[c]; hd1[c] = hd2[c]; hd2[c] = hdn;
                const float gxv = (hd0[c] + 2.0f * hd1[c]) + hd2[c] + shb;
                const float gyv = hs0[c] - hs2[c] + svb;
                nm += sqrtf(gxv * gxv + gyv * gyv);
                ngx += gxv; ngy += gyv;
            }
            const bool rMok = INTERIOR || ((ym >= 0) && (ym < H));
            if (!(rMok && cMok)) nm = 0.0f;
            s_mag[i & 1][im] = nm;
        }
        __syncthreads();

        /* ---- D: orientation + NMS + 5 outputs for row yo = y0+i-8 ---- */
        if ((t < TX) && (i >= 8)) {
            const int slC = (i - 1) & 1;   /* mag row yo   */
            const int slN = i & 1;         /* mag row yo+1 */
            const float mag = pm;
            const size_t p = pbase + (size_t)(i - 8) * W;

            gm_out[p] = mag;

            float go = atan2f(pgy, pgx) * (180.0f / 3.14159f);
            if (go < 0.0f) go = 360.0f + go;
            go = fmodf(go, 180.0f);
            const float orient = rintf(go / 45.0f) * 45.0f;
            orient_out[p] = orient;

            early_out[p]  = (mag < 10.0f) ? 0.0f : mag;

            const int k = (int)(orient * (1.0f / 45.0f) + 0.5f);   /* 0..4 */
            const int di = (k >= 1 && k <= 3) ? 1 : 0;
            const int dj = (k < 2) ? 1 : ((k == 2) ? 0 : -1);
            const float bias = (k < 4) ? d0b : d1b;

            const float nbv = s_mag[di ? slN : slC][t + 1 + dj];  /* OOB already 0 */
            const float val = mag - nbv + bias;
            const float th = (val > 0.0f) ? mag : 0.0f;
            thin_out[p]   = th;
            thresh_out[p] = (th < 10.0f) ? 0.0f : th;
        }

        pm = nm; pgx = ngx; pgy = ngy;
    }
}

__global__ __launch_bounds__(NT) void canny_kernel(
    const float* __restrict__ img,
    const float* __restrict__ bh_p,  const float* __restrict__ bv_p,
    const float* __restrict__ shb_p, const float* __restrict__ svb_p,
    const float* __restrict__ d0b_p, const float* __restrict__ d1b_p,
    float* __restrict__ out)
{
    __shared__ float s_img[CH][LW];
    __shared__ float s_bl[CH][LW];
    __shared__ float s_mag[2][LW];

    const int b  = blockIdx.z;
    const int x0 = blockIdx.x * TX;
    const int y0 = blockIdx.y * TY;
    const int t  = threadIdx.x;

    const float bh  = __ldg(bh_p),  bv  = __ldg(bv_p);
    const float shb = __ldg(shb_p), svb = __ldg(svb_p);
    const float d0b = __ldg(d0b_p), d1b = __ldg(d1b_p);

    const float* imgb = img + (size_t)b * CH * NPLANE;
    float* blb = out + (size_t)b * CH * NPLANE;

    const bool interior = (x0 >= 4) && (x0 + TX + 4 <= W) &&
                          (y0 >= 4) && (y0 + TY + 4 <= H);

    if (interior)
        canny_body<true >(imgb, blb, out, b, x0, y0, t,
                          bh, bv, shb, svb, d0b, d1b, s_img, s_bl, s_mag);
    else
        canny_body<false>(imgb, blb, out, b, x0, y0, t,
                          bh, bv, shb, svb, d0b, d1b, s_img, s_bl, s_mag);
}

/* ================================================================== */
extern "C" void kernel_launch(void* const* d_in, const int* in_sizes, int n_in,
                              void* d_out, int out_size)
{
    const float* img = (const float*)d_in[0];
    const float* bh  = (const float*)d_in[1];
    const float* bv  = (const float*)d_in[2];
    const float* shb = (const float*)d_in[3];
    const float* svb = (const float*)d_in[4];
    const float* d0b = (const float*)d_in[5];
    const float* d1b = (const float*)d_in[6];

    dim3 grid(W / TX, H / TY, BATCH);
    canny_kernel<<<grid, NT>>>(img, bh, bv, shb, svb, d0b, d1b, (float*)d_out);

    (void)in_sizes; (void)n_in; (void)out_size;
}